// round 16
// baseline (speedup 1.0000x reference)
#include <cuda_runtime.h>

// CTC loss forward. One CTA (6 warps, 192 thr) per batch element.
//   warp 0: forward alpha DP, t = 0..127   (linear domain, per-lane rescale)
//   warp 1: backward beta DP, t = 255..128
//   warps 2-5: sum of log2 Z_t, 64 rows each. Row-per-warp layout (lane l
//              loads float4 l of the row -> perfectly coalesced, 4 L1
//              wavefronts/LDG), ring depth 8 (full unroll-8, reg-resident).
// Combine at m=127: loglik_raw = sum_s alpha(s)*beta(s); subtract Z sum.
// DP warps load 2 scalars/step (blank: uniform LDG; label: gather), ring 8
// deep, full unroll-8, pointer-increment addressing.

#define TN 256
#define HT 128
#define CN 128
#define LN 32
#define PADV 127
#define LOG2E 1.4426950408889634f
#define NLN2 0.6931471805599453f

__device__ __forceinline__ float ex2(float x) {
    float r; asm("ex2.approx.f32 %0, %1;" : "=f"(r) : "f"(x)); return r;
}
__device__ __forceinline__ float lg2(float x) {
    float r; asm("lg2.approx.f32 %0, %1;" : "=f"(r) : "f"(x)); return r;
}

__global__ __launch_bounds__(192) void ctc_ws4_kernel(
    const int* __restrict__ yt, const float* __restrict__ yp,
    float* __restrict__ out)
{
    const unsigned FULL = 0xffffffffu;
    __shared__ float s_bo[LN], s_be[LN], s_off[LN];
    __shared__ float s_b0;
    __shared__ double s_z[4];

    const int tid = threadIdx.x;
    const int wid = tid >> 5;
    const int l = tid & 31;
    const int b = blockIdx.x;
    const float* __restrict__ rowf = yp + (size_t)b * TN * CN;
    const float4* __restrict__ row4 = (const float4*)rowf;

    if (wid >= 2) {
        // ---- Z warps: 64 contiguous rows each, row-per-warp, ring depth 8 -
        const int base = (wid - 2) * 64;
        const float4* p = row4 + (size_t)base * 32 + l;

        float4 rg[8];
        #pragma unroll
        for (int i = 0; i < 8; ++i) rg[i] = p[i * 32];

        double zsum = 0.0;
        for (int g = 0; g < 8; ++g) {            // 8 groups of 8 rows
            const bool pf = (g < 7);
            #pragma unroll
            for (int i = 0; i < 8; ++i) {
                const float4 v = rg[i];
                if (pf) rg[i] = p[((g + 1) * 8 + i) * 32];
                float s = ex2(v.x * LOG2E) + ex2(v.y * LOG2E)
                        + ex2(v.z * LOG2E) + ex2(v.w * LOG2E);
                #pragma unroll
                for (int o = 16; o; o >>= 1) s += __shfl_xor_sync(FULL, s, o);
                zsum += (double)lg2(s);
            }
        }
        if (l == 0) s_z[wid - 2] = zsum;
        __syncthreads();
    } else if (wid == 1) {
        // ---- backward beta, rows r = 255..128 -----------------------------
        const int lab = yt[b * LN + l];
        const unsigned msk = __ballot_sync(FULL, lab != PADV);
        const int len = __popc(msk);
        const int labn = __shfl_down_sync(FULL, lab, 1);
        const float skipD = (l < 31 && lab != labn) ? 1.0f : 0.0f;

        const float* pb_ptr = rowf + (TN - 1) * CN;        // row 255, class 0
        const float* pl_ptr = pb_ptr + lab;
        float xb[8], xl[8];
        #pragma unroll
        for (int i = 0; i < 8; ++i) {
            xb[i] = __ldg(pb_ptr - i * CN);
            xl[i] = __ldg(pl_ptr - i * CN);
        }
        pb_ptr -= 8 * CN; pl_ptr -= 8 * CN;

        float b_odd = (l == len - 1) ? 1.0f : 0.0f;
        float b_even = b_odd;
        float b0 = 0.0f, off = 0.0f, cD = 1.0f;

        for (int g = 0; g < HT / 8; ++g) {
            const bool pf = (g + 1 < HT / 8);
            #pragma unroll
            for (int i = 0; i < 8; ++i) {
                const float pl = ex2(xl[i] * LOG2E);
                const float pb = ex2(xb[i] * LOG2E);
                if (pf) {
                    xb[i] = __ldg(pb_ptr - i * CN);
                    xl[i] = __ldg(pl_ptr - i * CN);
                }

                const float g_odd = pl * b_odd;
                const float g_even = pb * b_even;
                float gd = __shfl_down_sync(FULL, g_odd, 1) * cD;
                gd = (l < 31) ? gd : 0.0f;
                b0 = pb * b0 + g_odd;                       // valid on lane 0
                const float n_odd  = g_odd + g_even + skipD * gd;
                const float n_even = g_even + gd;
                b_odd = n_odd; b_even = n_even;

                if ((i & 3) == 3) {
                    const float m = fmaxf(b_odd,
                        fmaxf(b_even, (l == 0) ? b0 : 0.0f));
                    int eb = (__float_as_int(m) >> 23) & 255;
                    int k = (eb == 0) ? 0 : (eb - 127);
                    k = (k > 120) ? 120 : k;
                    const float sc = __int_as_float((127 - k) << 23);
                    b_odd *= sc; b_even *= sc; b0 *= sc;
                    off += (float)k;
                    cD = ex2(__shfl_down_sync(FULL, off, 1) - off);
                }
            }
            pb_ptr -= 8 * CN; pl_ptr -= 8 * CN;
        }

        s_bo[l] = b_odd;
        s_be[l] = b_even;
        s_off[l] = off;
        if (l == 0) s_b0 = b0;
        __syncthreads();
    } else {
        // ---- forward alpha, t = 0..127 ------------------------------------
        const int lab = yt[b * LN + l];
        const int labp = __shfl_up_sync(FULL, lab, 1);
        const float skipf = (l >= 1 && lab != labp) ? 1.0f : 0.0f;

        const float* pb_ptr = rowf;                        // row 0, class 0
        const float* pl_ptr = rowf + lab;
        float xb[8], xl[8];
        #pragma unroll
        for (int i = 0; i < 8; ++i) {
            xb[i] = __ldg(pb_ptr + i * CN);
            xl[i] = __ldg(pl_ptr + i * CN);
        }
        pb_ptr += 8 * CN; pl_ptr += 8 * CN;

        float a_odd = 0.0f, a_even = 0.0f, off = 0.0f, c = 1.0f;
        float a0lin = 1.0f;

        for (int g = 0; g < HT / 8; ++g) {
            const bool pf = (g + 1 < HT / 8);
            #pragma unroll
            for (int i = 0; i < 8; ++i) {
                const float pl = ex2(xl[i] * LOG2E);
                const float pb = ex2(xb[i] * LOG2E);
                if (pf) {
                    xb[i] = __ldg(pb_ptr + i * CN);
                    xl[i] = __ldg(pl_ptr + i * CN);
                }

                const float e0 = a0lin;
                a0lin *= pb;

                float po = __shfl_up_sync(FULL, a_odd, 1);
                float pe = __shfl_up_sync(FULL, a_even, 1);
                pe = (l == 0) ? e0 : pe * c;
                const float pos = po * c * skipf;
                const float n_odd  = pl * (a_odd + pe + pos);
                const float n_even = pb * (a_even + a_odd);
                a_odd = n_odd; a_even = n_even;

                if ((i & 3) == 3) {
                    const float m = fmaxf(a_odd, a_even);
                    int eb = (__float_as_int(m) >> 23) & 255;
                    int k = (eb == 0) ? 0 : (eb - 127);
                    k = (k > 120) ? 120 : k;
                    const float sc = __int_as_float((127 - k) << 23);
                    a_odd *= sc; a_even *= sc; a0lin *= sc;
                    off += (float)k;
                    c = ex2(__shfl_up_sync(FULL, off, 1) - off);
                }
            }
            pb_ptr += 8 * CN; pl_ptr += 8 * CN;
        }

        __syncthreads();   // beta + Z results visible

        // combine: loglik_raw = sum_s alpha(s)*beta(s)
        float val = a_odd * s_bo[l] + a_even * s_be[l];
        float e = off + s_off[l];
        if (l == 0) val += a0lin * s_b0;
        float ll = lg2(fmaxf(val, 1e-45f)) + e;
        float mm = ll;
        #pragma unroll
        for (int o = 16; o; o >>= 1) mm = fmaxf(mm, __shfl_xor_sync(FULL, mm, o));
        float se = ex2(ll - mm);
        #pragma unroll
        for (int o = 16; o; o >>= 1) se += __shfl_xor_sync(FULL, se, o);
        if (l == 0) {
            const float llraw = mm + lg2(se);
            const float cumZ = (float)(s_z[0] + s_z[1] + s_z[2] + s_z[3]);
            out[b] = (cumZ - llraw) * NLN2;
        }
    }
}

extern "C" void kernel_launch(void* const* d_in, const int* in_sizes, int n_in,
                              void* d_out, int out_size) {
    const int* y_true = (const int*)d_in[0];     // [1024, 32] int32
    const float* y_pred = (const float*)d_in[1]; // [1024, 256, 128] float32
    float* out = (float*)d_out;                  // [1024] float32
    const int B = in_sizes[0] / LN;              // 1024
    ctc_ws4_kernel<<<B, 192>>>(y_true, y_pred, out);
}

// round 17
// speedup vs baseline: 1.4351x; 1.4351x over previous
#include <cuda_runtime.h>

// CTC loss forward. One CTA (6 warps, 192 thr) per batch element.
//   warp 0: forward alpha DP, t = 0..127   (linear domain, per-lane rescale)
//   warp 1: backward beta DP, t = 255..128
//   warps 2-5: sum of log2 Z_t, 64 rows each, 4 rows/iteration:
//       coalesced loads (load j = row j, lane l = float4 l: 4 wavefronts/LDG)
//       + in-register transpose-reduce (3 SHFL) + shared butterfly (3 SHFL)
//       -> one LG2 + one DADD per 4 rows. Ring depth 2 (8 float4 in flight).
// Combine at m=127: loglik_raw = sum_s alpha(s)*beta(s); subtract Z sum.
// DP warps load 2 scalars/step (blank: uniform LDG; label: gather), ring 8
// deep, full unroll-8, pointer-increment addressing.

#define TN 256
#define HT 128
#define CN 128
#define LN 32
#define PADV 127
#define LOG2E 1.4426950408889634f
#define NLN2 0.6931471805599453f

__device__ __forceinline__ float ex2(float x) {
    float r; asm("ex2.approx.f32 %0, %1;" : "=f"(r) : "f"(x)); return r;
}
__device__ __forceinline__ float lg2(float x) {
    float r; asm("lg2.approx.f32 %0, %1;" : "=f"(r) : "f"(x)); return r;
}

__global__ __launch_bounds__(192) void ctc_ws5_kernel(
    const int* __restrict__ yt, const float* __restrict__ yp,
    float* __restrict__ out)
{
    const unsigned FULL = 0xffffffffu;
    __shared__ float s_bo[LN], s_be[LN], s_off[LN];
    __shared__ float s_b0;
    __shared__ double s_z[4];

    const int tid = threadIdx.x;
    const int wid = tid >> 5;
    const int l = tid & 31;
    const int b = blockIdx.x;
    const float* __restrict__ rowf = yp + (size_t)b * TN * CN;
    const float4* __restrict__ row4 = (const float4*)rowf;

    if (wid >= 2) {
        // ---- Z warps: 64 rows, 4 rows/iter, coalesced + transpose-reduce --
        const int base = (wid - 2) * 64;
        const float4* p = row4 + (size_t)base * 32 + l;  // lane l = float4 l

        float4 v[2][4];
        #pragma unroll
        for (int j = 0; j < 4; ++j) v[0][j] = p[j * 32];
        #pragma unroll
        for (int j = 0; j < 4; ++j) v[1][j] = p[(4 + j) * 32];

        const bool bit0 = (l & 1), bit1 = ((l >> 1) & 1);
        double zacc = 0.0;                  // accumulates row-class (l&3)

        for (int it = 0; it < 16; ++it) {
            const int cu = it & 1;
            float s0, s1, s2, s3;
            {
                const float4 q = v[cu][0];
                s0 = ex2(q.x * LOG2E) + ex2(q.y * LOG2E)
                   + ex2(q.z * LOG2E) + ex2(q.w * LOG2E);
            }
            {
                const float4 q = v[cu][1];
                s1 = ex2(q.x * LOG2E) + ex2(q.y * LOG2E)
                   + ex2(q.z * LOG2E) + ex2(q.w * LOG2E);
            }
            {
                const float4 q = v[cu][2];
                s2 = ex2(q.x * LOG2E) + ex2(q.y * LOG2E)
                   + ex2(q.z * LOG2E) + ex2(q.w * LOG2E);
            }
            {
                const float4 q = v[cu][3];
                s3 = ex2(q.x * LOG2E) + ex2(q.y * LOG2E)
                   + ex2(q.z * LOG2E) + ex2(q.w * LOG2E);
            }
            if (it + 2 < 16) {
                #pragma unroll
                for (int j = 0; j < 4; ++j)
                    v[cu][j] = p[((it + 2) * 4 + j) * 32];
            }
            // stage 1 (xor 1): lane keeps rows {2*bit0, 2*bit0+1}
            const float u0 = bit0 ? s0 : s2;
            const float u1 = bit0 ? s1 : s3;
            const float t0 = (bit0 ? s2 : s0) + __shfl_xor_sync(FULL, u0, 1);
            const float t1 = (bit0 ? s3 : s1) + __shfl_xor_sync(FULL, u1, 1);
            // stage 2 (xor 2): lane keeps row 2*bit0 + bit1 (perm 0,2,1,3)
            const float u2 = bit1 ? t0 : t1;
            float w = (bit1 ? t1 : t0) + __shfl_xor_sync(FULL, u2, 2);
            // stage 3: butterfly over quads -> full row sum, uniform per l&3
            w += __shfl_xor_sync(FULL, w, 4);
            w += __shfl_xor_sync(FULL, w, 8);
            w += __shfl_xor_sync(FULL, w, 16);
            zacc += (double)lg2(w);
        }
        // lanes 0..3 hold disjoint row-class sums; combine them
        zacc += __shfl_xor_sync(FULL, zacc, 1);
        zacc += __shfl_xor_sync(FULL, zacc, 2);
        if (l == 0) s_z[wid - 2] = zacc;
        __syncthreads();
    } else if (wid == 1) {
        // ---- backward beta, rows r = 255..128 -----------------------------
        const int lab = yt[b * LN + l];
        const unsigned msk = __ballot_sync(FULL, lab != PADV);
        const int len = __popc(msk);
        const int labn = __shfl_down_sync(FULL, lab, 1);
        const float skipD = (l < 31 && lab != labn) ? 1.0f : 0.0f;

        const float* pb_ptr = rowf + (TN - 1) * CN;        // row 255, class 0
        const float* pl_ptr = pb_ptr + lab;
        float xb[8], xl[8];
        #pragma unroll
        for (int i = 0; i < 8; ++i) {
            xb[i] = __ldg(pb_ptr - i * CN);
            xl[i] = __ldg(pl_ptr - i * CN);
        }
        pb_ptr -= 8 * CN; pl_ptr -= 8 * CN;

        float b_odd = (l == len - 1) ? 1.0f : 0.0f;
        float b_even = b_odd;
        float b0 = 0.0f, off = 0.0f, cD = 1.0f;

        for (int g = 0; g < HT / 8; ++g) {
            const bool pf = (g + 1 < HT / 8);
            #pragma unroll
            for (int i = 0; i < 8; ++i) {
                const float pl = ex2(xl[i] * LOG2E);
                const float pb = ex2(xb[i] * LOG2E);
                if (pf) {
                    xb[i] = __ldg(pb_ptr - i * CN);
                    xl[i] = __ldg(pl_ptr - i * CN);
                }

                const float g_odd = pl * b_odd;
                const float g_even = pb * b_even;
                float gd = __shfl_down_sync(FULL, g_odd, 1) * cD;
                gd = (l < 31) ? gd : 0.0f;
                b0 = pb * b0 + g_odd;                       // valid on lane 0
                const float n_odd  = g_odd + g_even + skipD * gd;
                const float n_even = g_even + gd;
                b_odd = n_odd; b_even = n_even;

                if ((i & 3) == 3) {
                    const float m = fmaxf(b_odd,
                        fmaxf(b_even, (l == 0) ? b0 : 0.0f));
                    int eb = (__float_as_int(m) >> 23) & 255;
                    int k = (eb == 0) ? 0 : (eb - 127);
                    k = (k > 120) ? 120 : k;
                    const float sc = __int_as_float((127 - k) << 23);
                    b_odd *= sc; b_even *= sc; b0 *= sc;
                    off += (float)k;
                    cD = ex2(__shfl_down_sync(FULL, off, 1) - off);
                }
            }
            pb_ptr -= 8 * CN; pl_ptr -= 8 * CN;
        }

        s_bo[l] = b_odd;
        s_be[l] = b_even;
        s_off[l] = off;
        if (l == 0) s_b0 = b0;
        __syncthreads();
    } else {
        // ---- forward alpha, t = 0..127 ------------------------------------
        const int lab = yt[b * LN + l];
        const int labp = __shfl_up_sync(FULL, lab, 1);
        const float skipf = (l >= 1 && lab != labp) ? 1.0f : 0.0f;

        const float* pb_ptr = rowf;                        // row 0, class 0
        const float* pl_ptr = rowf + lab;
        float xb[8], xl[8];
        #pragma unroll
        for (int i = 0; i < 8; ++i) {
            xb[i] = __ldg(pb_ptr + i * CN);
            xl[i] = __ldg(pl_ptr + i * CN);
        }
        pb_ptr += 8 * CN; pl_ptr += 8 * CN;

        float a_odd = 0.0f, a_even = 0.0f, off = 0.0f, c = 1.0f;
        float a0lin = 1.0f;

        for (int g = 0; g < HT / 8; ++g) {
            const bool pf = (g + 1 < HT / 8);
            #pragma unroll
            for (int i = 0; i < 8; ++i) {
                const float pl = ex2(xl[i] * LOG2E);
                const float pb = ex2(xb[i] * LOG2E);
                if (pf) {
                    xb[i] = __ldg(pb_ptr + i * CN);
                    xl[i] = __ldg(pl_ptr + i * CN);
                }

                const float e0 = a0lin;
                a0lin *= pb;

                float po = __shfl_up_sync(FULL, a_odd, 1);
                float pe = __shfl_up_sync(FULL, a_even, 1);
                pe = (l == 0) ? e0 : pe * c;
                const float pos = po * c * skipf;
                const float n_odd  = pl * (a_odd + pe + pos);
                const float n_even = pb * (a_even + a_odd);
                a_odd = n_odd; a_even = n_even;

                if ((i & 3) == 3) {
                    const float m = fmaxf(a_odd, a_even);
                    int eb = (__float_as_int(m) >> 23) & 255;
                    int k = (eb == 0) ? 0 : (eb - 127);
                    k = (k > 120) ? 120 : k;
                    const float sc = __int_as_float((127 - k) << 23);
                    a_odd *= sc; a_even *= sc; a0lin *= sc;
                    off += (float)k;
                    c = ex2(__shfl_up_sync(FULL, off, 1) - off);
                }
            }
            pb_ptr += 8 * CN; pl_ptr += 8 * CN;
        }

        __syncthreads();   // beta + Z results visible

        // combine: loglik_raw = sum_s alpha(s)*beta(s)
        float val = a_odd * s_bo[l] + a_even * s_be[l];
        float e = off + s_off[l];
        if (l == 0) val += a0lin * s_b0;
        float ll = lg2(fmaxf(val, 1e-45f)) + e;
        float mm = ll;
        #pragma unroll
        for (int o = 16; o; o >>= 1) mm = fmaxf(mm, __shfl_xor_sync(FULL, mm, o));
        float se = ex2(ll - mm);
        #pragma unroll
        for (int o = 16; o; o >>= 1) se += __shfl_xor_sync(FULL, se, o);
        if (l == 0) {
            const float llraw = mm + lg2(se);
            const float cumZ = (float)(s_z[0] + s_z[1] + s_z[2] + s_z[3]);
            out[b] = (cumZ - llraw) * NLN2;
        }
    }
}

extern "C" void kernel_launch(void* const* d_in, const int* in_sizes, int n_in,
                              void* d_out, int out_size) {
    const int* y_true = (const int*)d_in[0];     // [1024, 32] int32
    const float* y_pred = (const float*)d_in[1]; // [1024, 256, 128] float32
    float* out = (float*)d_out;                  // [1024] float32
    const int B = in_sizes[0] / LN;              // 1024
    ctc_ws5_kernel<<<B, 192>>>(y_true, y_pred, out);
}